// round 13
// baseline (speedup 1.0000x reference)
#include <cuda_runtime.h>
#include <cuda_fp16.h>
#include <math.h>
#include <stdint.h>

#define D 1024
#define F 4096
#define MTOT 8192

typedef __half fp16;

// ---- scratch (static device globals: allocation-free) ----
__device__ fp16 g_x16[(size_t)MTOT * D];  // 16 MB
__device__ fp16 g_wfc[(size_t)F * D];     // 8 MB
__device__ fp16 g_h16[(size_t)MTOT * F];  // 64 MB
__device__ fp16 g_wp[(size_t)D * F];      // 8 MB
__device__ unsigned int g_max2[2];

// ===========================================================================
// helpers
// ===========================================================================
__device__ __forceinline__ uint32_t smem_u32(const void* p) {
    uint32_t a;
    asm("{ .reg .u64 t; cvta.to.shared.u64 t, %1; cvt.u32.u64 %0, t; }" : "=r"(a) : "l"(p));
    return a;
}
__device__ __forceinline__ void cp16(uint32_t s, const void* g) {
    asm volatile("cp.async.cg.shared.global [%0], [%1], 16;" :: "r"(s), "l"(g));
}
__device__ __forceinline__ void cp_commit() {
    asm volatile("cp.async.commit_group;");
}
__device__ __forceinline__ void cp_wait3() {
    asm volatile("cp.async.wait_group 3;");
}
__device__ __forceinline__ void ldsm4(uint32_t a, uint32_t& r0, uint32_t& r1,
                                      uint32_t& r2, uint32_t& r3) {
    asm volatile("ldmatrix.sync.aligned.m8n8.x4.shared.b16 {%0,%1,%2,%3}, [%4];"
                 : "=r"(r0), "=r"(r1), "=r"(r2), "=r"(r3) : "r"(a));
}
__device__ __forceinline__ void mma16816(float* c, const uint32_t* a, uint32_t b0, uint32_t b1) {
    asm volatile(
        "mma.sync.aligned.m16n8k16.row.col.f32.f16.f16.f32 "
        "{%0,%1,%2,%3}, {%4,%5,%6,%7}, {%8,%9}, {%0,%1,%2,%3};"
        : "+f"(c[0]), "+f"(c[1]), "+f"(c[2]), "+f"(c[3])
        : "r"(a[0]), "r"(a[1]), "r"(a[2]), "r"(a[3]), "r"(b0), "r"(b1));
}

// ===========================================================================
// pre-pass kernels
// ===========================================================================
__global__ void k_init_max() { g_max2[0] = 0u; g_max2[1] = 0u; }

// blockIdx.y selects tensor (0: W_fc, 1: W_proj); both are F*D floats.
__global__ void k_absmax2(const float* __restrict__ W0, const float* __restrict__ W1) {
    int sel = blockIdx.y;
    const float* W = sel ? W1 : W0;
    int n = F * D;
    float m = 0.f;
    int stride = gridDim.x * blockDim.x;
    for (int i = blockIdx.x * blockDim.x + threadIdx.x; i < n; i += stride)
        m = fmaxf(m, fabsf(W[i]));
    #pragma unroll
    for (int o = 16; o; o >>= 1) m = fmaxf(m, __shfl_xor_sync(0xffffffffu, m, o));
    __shared__ float sm[8];
    int lane = threadIdx.x & 31, w = threadIdx.x >> 5;
    if (lane == 0) sm[w] = m;
    __syncthreads();
    if (threadIdx.x == 0) {
        float mm = sm[0];
        for (int i = 1; i < 8; i++) mm = fmaxf(mm, sm[i]);
        atomicMax(&g_max2[sel], __float_as_uint(mm));
    }
}

// fakequant(W) + 2*B@A -> single fp16, row-major [out, K]
__global__ void k_quant_w(const float* __restrict__ W, const float* __restrict__ A,
                          const float* __restrict__ Bm, fp16* __restrict__ Wo,
                          int K, int sel) {
    int o = blockIdx.y;
    __shared__ float Bs[16];
    if (threadIdx.x < 16) Bs[threadIdx.x] = Bm[o * 16 + threadIdx.x];
    __syncthreads();
    float mx = __uint_as_float(g_max2[sel]);
    float scale = mx * (1.0f / 127.0f);
    float inv   = 127.0f / mx;
    int k = (blockIdx.x * blockDim.x + threadIdx.x) * 2;
    float w0 = W[(size_t)o * K + k], w1 = W[(size_t)o * K + k + 1];
    float q0 = fminf(fmaxf(rintf(w0 * inv), -128.f), 127.f) * scale;
    float q1 = fminf(fmaxf(rintf(w1 * inv), -128.f), 127.f) * scale;
    float a0 = 0.f, a1 = 0.f;
    #pragma unroll
    for (int r = 0; r < 16; r++) {
        a0 = fmaf(Bs[r], A[(size_t)r * K + k],     a0);
        a1 = fmaf(Bs[r], A[(size_t)r * K + k + 1], a1);
    }
    float v0 = q0 + 2.0f * a0, v1 = q1 + 2.0f * a1;
    *(__half2*)(Wo + (size_t)o * K + k) = __floats2half2_rn(v0, v1);
}

__global__ void k_convert_x(const float4* __restrict__ x, fp16* __restrict__ xo) {
    size_t i = (size_t)blockIdx.x * blockDim.x + threadIdx.x;
    float4 v = x[i];
    __half2* p = (__half2*)(xo + i * 4);
    p[0] = __floats2half2_rn(v.x, v.y);
    p[1] = __floats2half2_rn(v.z, v.w);
}

// ===========================================================================
// GEMM: C[M,N] = A[M,K] * B[N,K]^T + bias, pure fp16, fp32 accum
// CTA tile 128x128, BK=32, 5-stage cp.async pipeline, ONE barrier/iter,
// 2 CTAs/SM (occupancy experiment). 8 warps = 2(m) x 4(n), warp tile 64x32.
// MODE 0: epilogue bias + exact GELU -> fp16 H (row-major)
// MODE 1: epilogue bias -> fp32 out
// ===========================================================================
#define BK 32
#define RSB 80                        // 64B data + 16B pad
#define MAT_A (128 * RSB)             // 10240
#define MAT_Bm (128 * RSB)            // 10240
#define STAGE_B (MAT_A + MAT_Bm)      // 20480
#define NSTAGE 5
#define GSMEM (NSTAGE * STAGE_B)      // 102400

template <int MODE>
__global__ void __launch_bounds__(256, 2)
k_gemm(const fp16* __restrict__ Ax, const fp16* __restrict__ Bw,
       const float* __restrict__ bias, float* __restrict__ outf,
       fp16* __restrict__ outH, int K, int N) {
    extern __shared__ char smem[];
    uint32_t sb = smem_u32(smem);
    int tid = threadIdx.x, wid = tid >> 5, lane = tid & 31;
    int m0 = blockIdx.y * 128;
    int n0 = blockIdx.x * 128;
    int warp_m = (wid >> 2) * 64;
    int warp_n = (wid & 3) * 32;

    int r0i = tid >> 1;               // load row 0..127 (2 threads/row)
    int c0i = tid & 1;                // which pair of 16B chunks

    float acc[4][4][4];
    #pragma unroll
    for (int i = 0; i < 4; i++)
        #pragma unroll
        for (int j = 0; j < 4; j++)
            #pragma unroll
            for (int q = 0; q < 4; q++) acc[i][j][q] = 0.f;

    int KT = K / BK;

    uint32_t a_off[4], b_off[2];
    #pragma unroll
    for (int mi = 0; mi < 4; mi++)
        a_off[mi] = (uint32_t)((warp_m + mi * 16 + (lane & 15)) * RSB + (lane >> 4) * 16);
    #pragma unroll
    for (int g = 0; g < 2; g++)
        b_off[g] = (uint32_t)(MAT_A + (warp_n + g * 16 + (lane & 15)) * RSB + (lane >> 4) * 16);

    auto load_stage = [&](int slot, int kt) {
        uint32_t st = sb + slot * STAGE_B;
        int kb = kt * BK;
        // A: 128 rows x 4 chunks of 16B; 2 threads/row, 2 chunks each
        #pragma unroll
        for (int j = 0; j < 2; j++) {
            uint32_t s_off = (uint32_t)(r0i * RSB + (c0i * 2 + j) * 16);
            cp16(st + s_off, Ax + (size_t)(m0 + r0i) * K + kb + (c0i * 2 + j) * 8);
        }
        // B: 128 rows x 4 chunks
        #pragma unroll
        for (int j = 0; j < 2; j++) {
            uint32_t s_off = (uint32_t)(MAT_A + r0i * RSB + (c0i * 2 + j) * 16);
            cp16(st + s_off, Bw + (size_t)(n0 + r0i) * K + kb + (c0i * 2 + j) * 8);
        }
        cp_commit();
    };

    load_stage(0, 0);
    load_stage(1, 1);
    load_stage(2, 2);
    load_stage(3, 3);

    for (int kt = 0; kt < KT; kt++) {
        cp_wait3();
        __syncthreads();
        if (kt + 4 < KT) load_stage((kt + 4) % NSTAGE, kt + 4);

        uint32_t st = sb + (kt % NSTAGE) * STAGE_B;
        #pragma unroll
        for (int s = 0; s < 2; s++) {
            uint32_t ks = s * 32;
            uint32_t af[4][4], bf[2][4];
            #pragma unroll
            for (int g = 0; g < 2; g++)
                ldsm4(st + b_off[g] + ks, bf[g][0], bf[g][1], bf[g][2], bf[g][3]);
            #pragma unroll
            for (int mi = 0; mi < 4; mi++)
                ldsm4(st + a_off[mi] + ks, af[mi][0], af[mi][1], af[mi][2], af[mi][3]);
            #pragma unroll
            for (int mi = 0; mi < 4; mi++) {
                #pragma unroll
                for (int ni = 0; ni < 4; ni++) {
                    int g = ni >> 1, sel = ni & 1;
                    mma16816(acc[mi][ni], af[mi], bf[g][sel], bf[g][sel + 2]);
                }
            }
        }
        // no end-of-loop barrier: next iteration's top barrier orders the
        // slot reuse (writes only issued after that barrier).
    }

    // ---- epilogue ----
    int gid = lane >> 2, tig = lane & 3;
    #pragma unroll
    for (int mi = 0; mi < 4; mi++) {
        int row = m0 + warp_m + mi * 16 + gid;
        #pragma unroll
        for (int ni = 0; ni < 4; ni++) {
            int col = n0 + warp_n + ni * 8 + tig * 2;
            float bcol0 = __ldg(&bias[col]), bcol1 = __ldg(&bias[col + 1]);
            #pragma unroll
            for (int half = 0; half < 2; half++) {
                int rr = row + half * 8;
                float v0 = acc[mi][ni][half * 2 + 0] + bcol0;
                float v1 = acc[mi][ni][half * 2 + 1] + bcol1;
                if (MODE == 0) {
                    v0 = 0.5f * v0 * (1.0f + erff(v0 * 0.70710678118654752f));
                    v1 = 0.5f * v1 * (1.0f + erff(v1 * 0.70710678118654752f));
                    *(__half2*)(outH + (size_t)rr * N + col) = __floats2half2_rn(v0, v1);
                } else {
                    float2 v; v.x = v0; v.y = v1;
                    *(float2*)(outf + (size_t)rr * N + col) = v;
                }
            }
        }
    }
}

// ===========================================================================
extern "C" void kernel_launch(void* const* d_in, const int* in_sizes, int n_in,
                              void* d_out, int out_size) {
    const float* x      = (const float*)d_in[0];
    const float* W_fc   = (const float*)d_in[1];
    const float* b_fc   = (const float*)d_in[2];
    const float* A_fc   = (const float*)d_in[3];
    const float* B_fc   = (const float*)d_in[4];
    const float* W_proj = (const float*)d_in[5];
    const float* b_proj = (const float*)d_in[6];
    const float* A_proj = (const float*)d_in[7];
    const float* B_proj = (const float*)d_in[8];
    float* out = (float*)d_out;

    fp16 *x16, *wfc, *h16, *wp;
    cudaGetSymbolAddress((void**)&x16, g_x16);
    cudaGetSymbolAddress((void**)&wfc, g_wfc);
    cudaGetSymbolAddress((void**)&h16, g_h16);
    cudaGetSymbolAddress((void**)&wp,  g_wp);

    cudaFuncSetAttribute(k_gemm<0>, cudaFuncAttributeMaxDynamicSharedMemorySize, GSMEM);
    cudaFuncSetAttribute(k_gemm<1>, cudaFuncAttributeMaxDynamicSharedMemorySize, GSMEM);

    k_init_max<<<1, 32>>>();
    k_absmax2<<<dim3(128, 2), 256>>>(W_fc, W_proj);

    k_quant_w<<<dim3(D / 512, F), 256>>>(W_fc,   A_fc,   B_fc,   wfc, D, 0);
    k_quant_w<<<dim3(F / 512, D), 256>>>(W_proj, A_proj, B_proj, wp,  F, 1);
    k_convert_x<<<(MTOT * D / 4) / 256, 256>>>((const float4*)x, x16);

    // GEMM1: [8192,1024] x [4096,1024]^T -> GELU -> fp16 H
    k_gemm<0><<<dim3(F / 128, MTOT / 128), 256, GSMEM>>>(
        x16, wfc, b_fc, nullptr, h16, D, F);
    // GEMM2: [8192,4096] x [1024,4096]^T -> fp32 out
    k_gemm<1><<<dim3(D / 128, MTOT / 128), 256, GSMEM>>>(
        h16, wp, b_proj, out, nullptr, F, D);
}